// round 10
// baseline (speedup 1.0000x reference)
#include <cuda_runtime.h>
#include <cuda_bf16.h>
#include <cstdint>

#define NN 8192
#define INF_DIM 512
#define OUTF 64
#define ALPHA 0.2f

#define NSLICE 4
#define TI 64                     // i-rows per attn block
#define CJ 64                     // j per chunk
#define SLICE_J (NN / NSLICE)     // 2048
#define NCHUNK (SLICE_J / CJ)     // 32
#define PPITCH 68                 // p_sh [row][j] pitch (floats): 16B-aligned, conflict-free
#define HPITCH 68                 // hT_sh [c][j] pitch

typedef unsigned long long ull;

// ---------------- device scratch (no cudaMalloc allowed) -------------------
__device__ float g_h[NN * OUTF];                 // h = X @ W
__device__ float g_hT[OUTF * NN];                // h transposed [c][j]
__device__ float g_fs[NN];                       // s_i
__device__ float g_R[NN];                        // exp(0.8 s_i)
__device__ float4 g_tab[NN];                     // (d_j, exp(d_j), exp(0.2 d_j), 0)
__device__ float g_accD[NSLICE * NN * OUTF];     // partial att@h per slice
__device__ float g_accZ[NSLICE * NN];            // partial row sums per slice

// ---- packed f32x2 helpers ------------------------------------------------
__device__ __forceinline__ void ffma2(ull& d, ull a, ull b) {
    asm("fma.rn.f32x2 %0, %1, %2, %0;" : "+l"(d) : "l"(a), "l"(b));
}
__device__ __forceinline__ ull pack2(float x) {
    ull r; unsigned int u = __float_as_uint(x);
    asm("mov.b64 %0, {%1, %1};" : "=l"(r) : "r"(u));
    return r;
}
__device__ __forceinline__ float fold2(ull v) {
    return __uint_as_float((unsigned)v) + __uint_as_float((unsigned)(v >> 32));
}

// ---------------------------------------------------------------------------
// Kernel A: h = X @ W.  Tiled smem GEMM with FFMA2 (verified R4-R9).
// ---------------------------------------------------------------------------
__global__ void __launch_bounds__(256) gemm_h_kernel(const float* __restrict__ X,
                                                     const float* __restrict__ W) {
    __shared__ float w_sh[64 * 64];
    __shared__ float x_sh[64 * 65];

    const int tid = threadIdx.x;
    const int i0 = blockIdx.x * 64;
    const int rg = tid >> 4;
    const int cg = tid & 15;

    ull acc[4][2];
    #pragma unroll
    for (int r = 0; r < 4; ++r) { acc[r][0] = 0ull; acc[r][1] = 0ull; }

    const int xr = tid >> 2;
    const int xk = (tid & 3) * 16;

    for (int kt = 0; kt < INF_DIM; kt += 64) {
        const float4* wsrc = (const float4*)(W + (size_t)kt * OUTF);
        float4* wdst = (float4*)w_sh;
        #pragma unroll
        for (int t = 0; t < 4; ++t) wdst[t * 256 + tid] = wsrc[t * 256 + tid];

        const float4* xsrc = (const float4*)(X + (size_t)(i0 + xr) * INF_DIM + kt + xk);
        #pragma unroll
        for (int t = 0; t < 4; ++t) {
            float4 v = xsrc[t];
            x_sh[(xk + t * 4 + 0) * 65 + xr] = v.x;
            x_sh[(xk + t * 4 + 1) * 65 + xr] = v.y;
            x_sh[(xk + t * 4 + 2) * 65 + xr] = v.z;
            x_sh[(xk + t * 4 + 3) * 65 + xr] = v.w;
        }
        __syncthreads();

        #pragma unroll 4
        for (int k = 0; k < 64; ++k) {
            ull w0 = *(const ull*)(w_sh + k * 64 + cg * 2);
            ull w1 = *(const ull*)(w_sh + k * 64 + cg * 2 + 32);
            const float* xp = x_sh + k * 65 + rg * 4;
            #pragma unroll
            for (int r = 0; r < 4; ++r) {
                ull xx = pack2(xp[r]);
                ffma2(acc[r][0], xx, w0);
                ffma2(acc[r][1], xx, w1);
            }
        }
        __syncthreads();
    }

    #pragma unroll
    for (int r = 0; r < 4; ++r) {
        float* dst = g_h + (size_t)(i0 + rg * 4 + r) * OUTF + cg * 2;
        *(ull*)(dst) = acc[r][0];
        *(ull*)(dst + 32) = acc[r][1];
    }
}

// ---------------------------------------------------------------------------
// Kernel B: f_src/f_dst + factorized exp node terms (verified R5/R9).
//   wgt_ij = adj * ( s_i+d_j >= 0 ? exp(0.8 s_i)*exp(d_j) : exp(0.2 d_j) )
// ---------------------------------------------------------------------------
__global__ void __launch_bounds__(256) fsfd_kernel(const float* __restrict__ a) {
    int lane = threadIdx.x & 31;
    int row = blockIdx.x * 8 + (threadIdx.x >> 5);
    float h0 = g_h[(size_t)row * OUTF + lane];
    float h1 = g_h[(size_t)row * OUTF + lane + 32];
    float fs = h0 * a[lane] + h1 * a[lane + 32];
    float fd = h0 * a[64 + lane] + h1 * a[96 + lane];
    #pragma unroll
    for (int m = 16; m > 0; m >>= 1) {
        fs += __shfl_xor_sync(0xffffffffu, fs, m);
        fd += __shfl_xor_sync(0xffffffffu, fd, m);
    }
    if (lane == 0) {
        g_fs[row] = fs;
        g_R[row] = __expf(0.8f * fs);
        g_tab[row] = make_float4(fd, __expf(fd), __expf(ALPHA * fd), 0.f);
    }
}

// ---------------------------------------------------------------------------
// Kernel B2: transpose h -> g_hT [c][j] (fp32). 64x64 tiles, 256 threads.
// ---------------------------------------------------------------------------
__global__ void __launch_bounds__(256) hT_kernel() {
    __shared__ float tile[64 * 65];
    const int tid = threadIdx.x;
    const int j0 = blockIdx.x * 64;

    #pragma unroll
    for (int t = 0; t < 16; ++t) {
        int idx = t * 256 + tid;
        int jj = idx >> 6, c = idx & 63;
        tile[jj * 65 + c] = g_h[(size_t)(j0 + jj) * OUTF + c];
    }
    __syncthreads();
    #pragma unroll
    for (int t = 0; t < 16; ++t) {
        int idx = t * 256 + tid;
        int c = idx >> 6, jj = idx & 63;
        g_hT[(size_t)c * NN + j0 + jj] = tile[jj * 65 + c];
    }
}

// ---------------------------------------------------------------------------
// Kernel C: fused attn.  128 threads, TI=64, CJ=64, NSLICE=4 (grid 128x4).
//   stage 1: thread (row = tid&63, half = tid>>6) -> 32 weights, STS.128
//            into row-major p_sh[row][j]; z in registers.
//   stage 2: thread = (rg = tid>>3: 4 rows, cg = tid&7: cols cg+8t).
//            FFMA2 with j-pairs in the two lanes:
//              acc.lane0 += p[r][j]  * hT[c][j]
//              acc.lane1 += p[r][j+1]* hT[c][j+1]
//            operands via LDS.128 (ulonglong2), zero packing movs.
//            Fold lanes once in the epilogue.
// ---------------------------------------------------------------------------
__global__ void __launch_bounds__(128, 3) attn_kernel(const int* __restrict__ adj) {
    __shared__ float hT_sh[OUTF * HPITCH];   // [c][j]  17.4KB
    __shared__ float p_sh[TI * PPITCH];      // [row][j] 17.4KB
    __shared__ float z_part[128];

    const int tid = threadIdx.x;
    const int i0 = blockIdx.x * TI;
    const int slice = blockIdx.y;
    const int jbase = slice * SLICE_J;

    // stage-1 identity
    const int row = tid & 63;
    const int half = tid >> 6;
    const float neg_s = -g_fs[i0 + row];
    const float R_i = g_R[i0 + row];
    float z_acc = 0.f;

    // stage-2 identity
    const int rg = tid >> 3;                 // 16 rowgroups x 4 rows
    const int cg = tid & 7;                  // cols cg + 8t, t=0..7

    ull acc[4][8];
    #pragma unroll
    for (int r = 0; r < 4; ++r)
        #pragma unroll
        for (int t = 0; t < 8; ++t) acc[r][t] = 0ull;

    for (int ch = 0; ch < NCHUNK; ++ch) {
        const int j0 = jbase + ch * CJ;
        __syncthreads();   // prev stage-2 done: safe to overwrite hT_sh/p_sh

        // ---- load hT tile: 64c x 64j floats = 1024 float4, 8 per thread ----
        #pragma unroll
        for (int t = 0; t < 8; ++t) {
            int idx = t * 128 + tid;
            int c = idx >> 4, seg = idx & 15;
            float4 v = *(const float4*)(g_hT + (size_t)c * NN + j0 + seg * 4);
            *(float4*)(&hT_sh[c * HPITCH + seg * 4]) = v;
        }

        // ---- stage 1: weights -> p_sh[row][j] (STS.128), z in regs ----
        {
            const int4* ap = (const int4*)(adj + (size_t)(i0 + row) * NN + j0 + half * 32);
            int4 av[8];
            #pragma unroll
            for (int t = 0; t < 8; ++t) av[t] = ap[t];
            float zc = 0.f;
            #pragma unroll
            for (int t = 0; t < 8; ++t) {
                const int jl = half * 32 + t * 4;
                float4 b0 = g_tab[j0 + jl + 0];
                float4 b1 = g_tab[j0 + jl + 1];
                float4 b2 = g_tab[j0 + jl + 2];
                float4 b3 = g_tab[j0 + jl + 3];
                float sel0 = (b0.x >= neg_s) ? R_i * b0.y : b0.z;
                float sel1 = (b1.x >= neg_s) ? R_i * b1.y : b1.z;
                float sel2 = (b2.x >= neg_s) ? R_i * b2.y : b2.z;
                float sel3 = (b3.x >= neg_s) ? R_i * b3.y : b3.z;
                float w0 = (av[t].x != 0) ? sel0 : 0.f;
                float w1 = (av[t].y != 0) ? sel1 : 0.f;
                float w2 = (av[t].z != 0) ? sel2 : 0.f;
                float w3 = (av[t].w != 0) ? sel3 : 0.f;
                *(float4*)(&p_sh[row * PPITCH + jl]) = make_float4(w0, w1, w2, w3);
                zc += (w0 + w1) + (w2 + w3);
            }
            z_acc += zc;
        }
        __syncthreads();

        // ---- stage 2: acc += P tile x hT tile, j-pairs in FFMA2 lanes ----
        {
            const float* pb = p_sh + (rg * 4) * PPITCH;
            const float* hb = hT_sh + cg * HPITCH;
            #pragma unroll 4
            for (int j = 0; j < CJ; j += 4) {
                ulonglong2 pr[4], hc[8];
                #pragma unroll
                for (int r = 0; r < 4; ++r)
                    pr[r] = *(const ulonglong2*)(pb + r * PPITCH + j);
                #pragma unroll
                for (int t = 0; t < 8; ++t)
                    hc[t] = *(const ulonglong2*)(hb + t * 8 * HPITCH + j);
                #pragma unroll
                for (int r = 0; r < 4; ++r)
                    #pragma unroll
                    for (int t = 0; t < 8; ++t)
                        ffma2(acc[r][t], pr[r].x, hc[t].x);
                #pragma unroll
                for (int r = 0; r < 4; ++r)
                    #pragma unroll
                    for (int t = 0; t < 8; ++t)
                        ffma2(acc[r][t], pr[r].y, hc[t].y);
            }
        }
    }

    // ---- epilogue: fold lanes, store partials ----
    #pragma unroll
    for (int r = 0; r < 4; ++r) {
        float* dst = g_accD + ((size_t)slice * NN + i0 + rg * 4 + r) * OUTF;
        #pragma unroll
        for (int t = 0; t < 8; ++t)
            dst[cg + 8 * t] = fold2(acc[r][t]);
    }
    z_part[tid] = z_acc;
    __syncthreads();
    if (tid < TI)
        g_accZ[(size_t)slice * NN + i0 + tid] = z_part[tid] + z_part[tid + 64];
}

// ---------------------------------------------------------------------------
// Kernel D: combine slices, normalize, ELU, store.
// ---------------------------------------------------------------------------
__global__ void __launch_bounds__(256) combine_kernel(float* __restrict__ out) {
    int idx = blockIdx.x * 256 + threadIdx.x;
    int i = idx >> 6;
    float s = 0.f, z = 0.f;
    #pragma unroll
    for (int k = 0; k < NSLICE; ++k) {
        s += g_accD[(size_t)k * NN * OUTF + idx];
        z += g_accZ[(size_t)k * NN + i];
    }
    float v = s / z;
    v = (v > 0.f) ? v : expm1f(v);
    out[idx] = v;
}

// ---------------------------------------------------------------------------
extern "C" void kernel_launch(void* const* d_in, const int* in_sizes, int n_in,
                              void* d_out, int out_size) {
    const float* X = (const float*)d_in[0];   // [8192, 512] f32
    const int* adj = (const int*)d_in[1];     // [8192, 8192] i32
    const float* W = (const float*)d_in[2];   // [512, 64] f32
    const float* a = (const float*)d_in[3];   // [128, 1] f32
    float* out = (float*)d_out;               // [8192, 64] f32

    gemm_h_kernel<<<NN / 64, 256>>>(X, W);
    fsfd_kernel<<<NN / 8, 256>>>(a);
    hT_kernel<<<NN / 64, 256>>>();
    attn_kernel<<<dim3(NN / TI, NSLICE), 128>>>(adj);
    combine_kernel<<<NN * OUTF / 256, 256>>>(out);
}

// round 12
// speedup vs baseline: 2.5754x; 2.5754x over previous
#include <cuda_runtime.h>
#include <cuda_bf16.h>
#include <cstdint>

#define NN 8192
#define INF_DIM 512
#define OUTF 64
#define ALPHA 0.2f

#define NSLICE 4
#define SLICE_J (NN / NSLICE)     // 2048
#define TI 128                    // i-rows per attn block (8 warps x m16)
#define CJ 64                     // j per chunk
#define NCHUNK (SLICE_J / CJ)     // 32
#define NJT (NN / 16)             // 512 j-tiles (k16)
#define NNT (OUTF / 8)            // 8 n-tiles

typedef unsigned long long ull;

// ---------------- device scratch (no cudaMalloc allowed) -------------------
__device__ float g_h[NN * OUTF];                 // h = X @ W
__device__ float g_fs[NN];                       // s_i
__device__ float g_R[NN];                        // exp(0.8 s_i)
__device__ float4 g_tab[NN];                     // (d_j, exp(d_j), exp(0.2 d_j), 0)
__device__ uint2 g_Bhi[NJT * NNT * 32];          // B fragments (bf16 hi), per-lane
__device__ uint2 g_Blo[NJT * NNT * 32];          // B fragments (bf16 lo residual)
__device__ float g_accD[NSLICE * NN * OUTF];     // partial att@h per slice
__device__ float g_accZ[NSLICE * NN];            // partial row sums per slice

// ---- helpers --------------------------------------------------------------
__device__ __forceinline__ void ffma2(ull& d, ull a, ull b) {
    asm("fma.rn.f32x2 %0, %1, %2, %0;" : "+l"(d) : "l"(a), "l"(b));
}
__device__ __forceinline__ ull pack2(float x) {
    ull r; unsigned int u = __float_as_uint(x);
    asm("mov.b64 %0, {%1, %1};" : "=l"(r) : "r"(u));
    return r;
}
// pack {lo=b, hi=a} as bf16x2
__device__ __forceinline__ uint32_t bf2(float a, float b) {
    uint32_t r;
    asm("cvt.rn.bf16x2.f32 %0, %1, %2;" : "=r"(r) : "f"(a), "f"(b));
    return r;
}
__device__ __forceinline__ void mma16816(float* c, const uint32_t* a,
                                         uint32_t b0, uint32_t b1) {
    asm volatile(
        "mma.sync.aligned.m16n8k16.row.col.f32.bf16.bf16.f32 "
        "{%0,%1,%2,%3}, {%4,%5,%6,%7}, {%8,%9}, {%0,%1,%2,%3};"
        : "+f"(c[0]), "+f"(c[1]), "+f"(c[2]), "+f"(c[3])
        : "r"(a[0]), "r"(a[1]), "r"(a[2]), "r"(a[3]), "r"(b0), "r"(b1));
}

// ---------------------------------------------------------------------------
// Kernel A: h = X @ W.  Tiled smem GEMM with FFMA2 (verified R4-R10).
// ---------------------------------------------------------------------------
__global__ void __launch_bounds__(256) gemm_h_kernel(const float* __restrict__ X,
                                                     const float* __restrict__ W) {
    __shared__ float w_sh[64 * 64];
    __shared__ float x_sh[64 * 65];

    const int tid = threadIdx.x;
    const int i0 = blockIdx.x * 64;
    const int rg = tid >> 4;
    const int cg = tid & 15;

    ull acc[4][2];
    #pragma unroll
    for (int r = 0; r < 4; ++r) { acc[r][0] = 0ull; acc[r][1] = 0ull; }

    const int xr = tid >> 2;
    const int xk = (tid & 3) * 16;

    for (int kt = 0; kt < INF_DIM; kt += 64) {
        const float4* wsrc = (const float4*)(W + (size_t)kt * OUTF);
        float4* wdst = (float4*)w_sh;
        #pragma unroll
        for (int t = 0; t < 4; ++t) wdst[t * 256 + tid] = wsrc[t * 256 + tid];

        const float4* xsrc = (const float4*)(X + (size_t)(i0 + xr) * INF_DIM + kt + xk);
        #pragma unroll
        for (int t = 0; t < 4; ++t) {
            float4 v = xsrc[t];
            x_sh[(xk + t * 4 + 0) * 65 + xr] = v.x;
            x_sh[(xk + t * 4 + 1) * 65 + xr] = v.y;
            x_sh[(xk + t * 4 + 2) * 65 + xr] = v.z;
            x_sh[(xk + t * 4 + 3) * 65 + xr] = v.w;
        }
        __syncthreads();

        #pragma unroll 4
        for (int k = 0; k < 64; ++k) {
            ull w0 = *(const ull*)(w_sh + k * 64 + cg * 2);
            ull w1 = *(const ull*)(w_sh + k * 64 + cg * 2 + 32);
            const float* xp = x_sh + k * 65 + rg * 4;
            #pragma unroll
            for (int r = 0; r < 4; ++r) {
                ull xx = pack2(xp[r]);
                ffma2(acc[r][0], xx, w0);
                ffma2(acc[r][1], xx, w1);
            }
        }
        __syncthreads();
    }

    #pragma unroll
    for (int r = 0; r < 4; ++r) {
        float* dst = g_h + (size_t)(i0 + rg * 4 + r) * OUTF + cg * 2;
        *(ull*)(dst) = acc[r][0];
        *(ull*)(dst + 32) = acc[r][1];
    }
}

// ---------------------------------------------------------------------------
// Kernel B: f_src/f_dst + factorized exp node terms (verified R5-R10).
//   wgt_ij = adj * ( s_i+d_j >= 0 ? exp(0.8 s_i)*exp(d_j) : exp(0.2 d_j) )
// ---------------------------------------------------------------------------
__global__ void __launch_bounds__(256) fsfd_kernel(const float* __restrict__ a) {
    int lane = threadIdx.x & 31;
    int row = blockIdx.x * 8 + (threadIdx.x >> 5);
    float h0 = g_h[(size_t)row * OUTF + lane];
    float h1 = g_h[(size_t)row * OUTF + lane + 32];
    float fs = h0 * a[lane] + h1 * a[lane + 32];
    float fd = h0 * a[64 + lane] + h1 * a[96 + lane];
    #pragma unroll
    for (int m = 16; m > 0; m >>= 1) {
        fs += __shfl_xor_sync(0xffffffffu, fs, m);
        fd += __shfl_xor_sync(0xffffffffu, fd, m);
    }
    if (lane == 0) {
        g_fs[row] = fs;
        g_R[row] = __expf(0.8f * fs);
        g_tab[row] = make_float4(fd, __expf(fd), __expf(ALPHA * fd), 0.f);
    }
}

// ---------------------------------------------------------------------------
// Kernel B2: precompute B fragments (h as bf16 hi/lo) in mma per-lane order.
//   tile (jt, nt), lane l (g=l>>2, q=l&3):
//     b0 = { h[jt*16+2q][nt*8+g], h[jt*16+2q+1][..] }, b1 = same at k+8.
// ---------------------------------------------------------------------------
__global__ void __launch_bounds__(256) bfrag_kernel() {
    int idx = blockIdx.x * 256 + threadIdx.x;     // tile*32 + lane
    int lane = idx & 31, tile = idx >> 5;
    int jt = tile >> 3, nt = tile & 7;
    int g = lane >> 2, q = lane & 3;
    int c = nt * 8 + g;
    int j = jt * 16 + 2 * q;

    float v0 = g_h[(size_t)(j + 0) * OUTF + c];
    float v1 = g_h[(size_t)(j + 1) * OUTF + c];
    float v8 = g_h[(size_t)(j + 8) * OUTF + c];
    float v9 = g_h[(size_t)(j + 9) * OUTF + c];

    uint32_t h0 = bf2(v1, v0);
    uint32_t h1 = bf2(v9, v8);
    float r0 = v0 - __uint_as_float(h0 << 16);
    float r1 = v1 - __uint_as_float(h0 & 0xffff0000u);
    float r8 = v8 - __uint_as_float(h1 << 16);
    float r9 = v9 - __uint_as_float(h1 & 0xffff0000u);

    g_Bhi[idx] = make_uint2(h0, h1);
    g_Blo[idx] = make_uint2(bf2(r1, r0), bf2(r9, r8));
}

// ---------------------------------------------------------------------------
// Kernel C: tensor-core attn.  256 threads = 8 warps, warp = m16 strip.
//   Each thread computes the 8 weights of its OWN mma A-fragment in regs
//   (rows g,g+8; k = 2q,2q+1,2q+8,2q+9) -> bf16 hi/lo -> 3-pass m16n8k16.
//   Z: per-thread fp32 partials + quad shfl at the end.  No P smem, and no
//   per-chunk barriers (tab preloaded for the whole slice).
// ---------------------------------------------------------------------------
__global__ void __launch_bounds__(256, 2) attn_kernel(const int* __restrict__ adj) {
    __shared__ float4 tab_sh[SLICE_J];            // 32KB

    const int tid = threadIdx.x;
    const int w = tid >> 5, lane = tid & 31;
    const int g = lane >> 2, q = lane & 3;
    const int i0 = blockIdx.x * TI;
    const int slice = blockIdx.y;
    const int jbase = slice * SLICE_J;

    #pragma unroll
    for (int t = 0; t < SLICE_J / 256; ++t)
        tab_sh[t * 256 + tid] = g_tab[jbase + t * 256 + tid];
    __syncthreads();

    const int ra = i0 + w * 16 + g;
    const int rb = ra + 8;
    const float nsa = -g_fs[ra], Ra = g_R[ra];
    const float nsb = -g_fs[rb], Rb = g_R[rb];
    const int* adjra = adj + (size_t)ra * NN + jbase;
    const int* adjrb = adj + (size_t)rb * NN + jbase;
    float za = 0.f, zb = 0.f;

    float acc[NNT][4];
    #pragma unroll
    for (int nt = 0; nt < NNT; ++nt)
        #pragma unroll
        for (int t = 0; t < 4; ++t) acc[nt][t] = 0.f;

    for (int ch = 0; ch < NCHUNK; ++ch) {
        const int j0l = ch * CJ;
        #pragma unroll
        for (int kt = 0; kt < 4; ++kt) {
            const int jj = j0l + kt * 16 + 2 * q;

            float4 tA = tab_sh[jj];
            float4 tB = tab_sh[jj + 1];
            float4 tC = tab_sh[jj + 8];
            float4 tD = tab_sh[jj + 9];
            int2 mAa = *(const int2*)(adjra + jj);
            int2 mCa = *(const int2*)(adjra + jj + 8);
            int2 mAb = *(const int2*)(adjrb + jj);
            int2 mCb = *(const int2*)(adjrb + jj + 8);

            float wAa = (mAa.x != 0) ? ((tA.x >= nsa) ? Ra * tA.y : tA.z) : 0.f;
            float wBa = (mAa.y != 0) ? ((tB.x >= nsa) ? Ra * tB.y : tB.z) : 0.f;
            float wCa = (mCa.x != 0) ? ((tC.x >= nsa) ? Ra * tC.y : tC.z) : 0.f;
            float wDa = (mCa.y != 0) ? ((tD.x >= nsa) ? Ra * tD.y : tD.z) : 0.f;
            float wAb = (mAb.x != 0) ? ((tA.x >= nsb) ? Rb * tA.y : tA.z) : 0.f;
            float wBb = (mAb.y != 0) ? ((tB.x >= nsb) ? Rb * tB.y : tB.z) : 0.f;
            float wCb = (mCb.x != 0) ? ((tC.x >= nsb) ? Rb * tC.y : tC.z) : 0.f;
            float wDb = (mCb.y != 0) ? ((tD.x >= nsb) ? Rb * tD.y : tD.z) : 0.f;

            za += (wAa + wBa) + (wCa + wDa);
            zb += (wAb + wBb) + (wCb + wDb);

            uint32_t ahi[4], alo[4];
            ahi[0] = bf2(wBa, wAa);
            ahi[1] = bf2(wBb, wAb);
            ahi[2] = bf2(wDa, wCa);
            ahi[3] = bf2(wDb, wCb);
            {
                float lAa = wAa - __uint_as_float(ahi[0] << 16);
                float lBa = wBa - __uint_as_float(ahi[0] & 0xffff0000u);
                float lAb = wAb - __uint_as_float(ahi[1] << 16);
                float lBb = wBb - __uint_as_float(ahi[1] & 0xffff0000u);
                float lCa = wCa - __uint_as_float(ahi[2] << 16);
                float lDa = wDa - __uint_as_float(ahi[2] & 0xffff0000u);
                float lCb = wCb - __uint_as_float(ahi[3] << 16);
                float lDb = wDb - __uint_as_float(ahi[3] & 0xffff0000u);
                alo[0] = bf2(lBa, lAa);
                alo[1] = bf2(lBb, lAb);
                alo[2] = bf2(lDa, lCa);
                alo[3] = bf2(lDb, lCb);
            }

            const size_t tb = ((size_t)((jbase + j0l) >> 4) + kt) * 256 + lane;
            #pragma unroll
            for (int nt = 0; nt < NNT; ++nt) {
                uint2 bh = g_Bhi[tb + nt * 32];
                uint2 bl = g_Blo[tb + nt * 32];
                mma16816(acc[nt], ahi, bh.x, bh.y);
                mma16816(acc[nt], alo, bh.x, bh.y);
                mma16816(acc[nt], ahi, bl.x, bl.y);
            }
        }
    }

    // ---- epilogue: store D partials + quad-reduced Z ----
    float* da = g_accD + ((size_t)slice * NN + ra) * OUTF;
    float* db = g_accD + ((size_t)slice * NN + rb) * OUTF;
    #pragma unroll
    for (int nt = 0; nt < NNT; ++nt) {
        *(float2*)(da + nt * 8 + 2 * q) = make_float2(acc[nt][0], acc[nt][1]);
        *(float2*)(db + nt * 8 + 2 * q) = make_float2(acc[nt][2], acc[nt][3]);
    }
    za += __shfl_xor_sync(0xffffffffu, za, 1);
    za += __shfl_xor_sync(0xffffffffu, za, 2);
    zb += __shfl_xor_sync(0xffffffffu, zb, 1);
    zb += __shfl_xor_sync(0xffffffffu, zb, 2);
    if (q == 0) {
        g_accZ[(size_t)slice * NN + ra] = za;
        g_accZ[(size_t)slice * NN + rb] = zb;
    }
}

// ---------------------------------------------------------------------------
// Kernel D: combine slices, normalize, ELU, store.
// ---------------------------------------------------------------------------
__global__ void __launch_bounds__(256) combine_kernel(float* __restrict__ out) {
    int idx = blockIdx.x * 256 + threadIdx.x;
    int i = idx >> 6;
    float s = 0.f, z = 0.f;
    #pragma unroll
    for (int k = 0; k < NSLICE; ++k) {
        s += g_accD[(size_t)k * NN * OUTF + idx];
        z += g_accZ[(size_t)k * NN + i];
    }
    float v = s / z;
    v = (v > 0.f) ? v : expm1f(v);
    out[idx] = v;
}

// ---------------------------------------------------------------------------
extern "C" void kernel_launch(void* const* d_in, const int* in_sizes, int n_in,
                              void* d_out, int out_size) {
    const float* X = (const float*)d_in[0];   // [8192, 512] f32
    const int* adj = (const int*)d_in[1];     // [8192, 8192] i32
    const float* W = (const float*)d_in[2];   // [512, 64] f32
    const float* a = (const float*)d_in[3];   // [128, 1] f32
    float* out = (float*)d_out;               // [8192, 64] f32

    gemm_h_kernel<<<NN / 64, 256>>>(X, W);
    fsfd_kernel<<<NN / 8, 256>>>(a);
    bfrag_kernel<<<NJT * NNT * 32 / 256, 256>>>();
    attn_kernel<<<dim3(NN / TI, NSLICE), 256>>>(adj);
    combine_kernel<<<NN * OUTF / 256, 256>>>(out);
}